// round 1
// baseline (speedup 1.0000x reference)
#include <cuda_runtime.h>
#include <math.h>
#include <stdint.h>

// Problem constants
#define LL   2048
#define BBATCH 4
#define EE   512
#define HH   8
#define HDD  64
#define HIDD 2048
#define TT   (LL*BBATCH)   // 8192 tokens

// ---------------- scratch (no allocations allowed) ----------------
__device__ float g_x0[TT*EE];        // x + pe
__device__ float g_qkv[TT*3*EE];     // qkv projection
__device__ float g_att[TT*EE];       // attention out; later reused as ff out
__device__ float g_proj[TT*EE];      // out-proj result
__device__ float g_x1[TT*EE];        // after first LN
__device__ float g_h[TT*HIDD];       // ffn hidden

// ---------------- kernel 1: positional-encoding add ----------------
__global__ void pe_add_kernel(const float* __restrict__ x, float* __restrict__ out) {
    int i = blockIdx.x * blockDim.x + threadIdx.x;
    if (i >= TT*EE) return;
    int e = i & (EE - 1);
    int b = (i / EE) & (BBATCH - 1);
    // even e: sin((b+1)*10000^(-e/E)); odd e: cos((b+1)*10000^(-(e+1)/E))
    float ef = (e & 1) ? (float)(e + 1) : (float)e;
    // 10000^(-ef/512) = exp(-ef * ln(10000)/512)
    float freq = expf(-ef * (9.210340371976184f / 512.0f));
    float arg = (float)(b + 1) * freq;
    float pe = (e & 1) ? cosf(arg) : sinf(arg);
    out[i] = x[i] + pe;
}

// ---------------- kernel 2: SGEMM  C[M,N] = A[M,K] * W[N,K]^T + bias (+GELU) ----
// BM=BN=128, BK=8, 256 threads, 8x8 per-thread tile. M,N multiples of 128, K of 8.
__device__ __forceinline__ float gelu_exact(float v) {
    return 0.5f * v * (1.0f + erff(v * 0.70710678118654752f));
}

template <int GELU>
__global__ void __launch_bounds__(256)
sgemm_nt(const float* __restrict__ A, const float* __restrict__ W,
         const float* __restrict__ bias, float* __restrict__ C,
         int M, int N, int K) {
    __shared__ float As[8][128];
    __shared__ float Bs[8][128];

    int tid = threadIdx.x;
    int tx = tid & 15;          // 0..15 -> col group
    int ty = tid >> 4;          // 0..15 -> row group
    int rowBase = ty * 8;
    int colBase = tx * 8;
    int bRow = blockIdx.y * 128;
    int bCol = blockIdx.x * 128;

    int lr = tid >> 1;          // 0..127: tile row to load
    int lc = (tid & 1) * 4;     // 0 or 4: k-offset (float4)

    const float* Ag = A + (size_t)(bRow + lr) * K + lc;
    const float* Wg = W + (size_t)(bCol + lr) * K + lc;

    float acc[8][8];
#pragma unroll
    for (int i = 0; i < 8; i++)
#pragma unroll
        for (int j = 0; j < 8; j++) acc[i][j] = 0.0f;

    float4 a_next = *(const float4*)Ag;
    float4 b_next = *(const float4*)Wg;

    for (int k0 = 0; k0 < K; k0 += 8) {
        As[lc + 0][lr] = a_next.x; As[lc + 1][lr] = a_next.y;
        As[lc + 2][lr] = a_next.z; As[lc + 3][lr] = a_next.w;
        Bs[lc + 0][lr] = b_next.x; Bs[lc + 1][lr] = b_next.y;
        Bs[lc + 2][lr] = b_next.z; Bs[lc + 3][lr] = b_next.w;
        __syncthreads();

        if (k0 + 8 < K) {
            a_next = *(const float4*)(Ag + k0 + 8);
            b_next = *(const float4*)(Wg + k0 + 8);
        }

#pragma unroll
        for (int kk = 0; kk < 8; kk++) {
            float4 a0 = *(const float4*)&As[kk][rowBase];
            float4 a1 = *(const float4*)&As[kk][rowBase + 4];
            float4 b0 = *(const float4*)&Bs[kk][colBase];
            float4 b1 = *(const float4*)&Bs[kk][colBase + 4];
            float av[8] = {a0.x, a0.y, a0.z, a0.w, a1.x, a1.y, a1.z, a1.w};
            float bv[8] = {b0.x, b0.y, b0.z, b0.w, b1.x, b1.y, b1.z, b1.w};
#pragma unroll
            for (int i = 0; i < 8; i++)
#pragma unroll
                for (int j = 0; j < 8; j++)
                    acc[i][j] = fmaf(av[i], bv[j], acc[i][j]);
        }
        __syncthreads();
    }

    float bb[8];
#pragma unroll
    for (int j = 0; j < 8; j++) bb[j] = bias[bCol + colBase + j];

#pragma unroll
    for (int i = 0; i < 8; i++) {
        size_t row = (size_t)(bRow + rowBase + i);
        float v[8];
#pragma unroll
        for (int j = 0; j < 8; j++) {
            float t = acc[i][j] + bb[j];
            v[j] = GELU ? gelu_exact(t) : t;
        }
        float4 o0 = {v[0], v[1], v[2], v[3]};
        float4 o1 = {v[4], v[5], v[6], v[7]};
        *(float4*)&C[row * N + bCol + colBase]     = o0;
        *(float4*)&C[row * N + bCol + colBase + 4] = o1;
    }
}

// ---------------- kernel 3: flash attention (fp32, no mask) ----------------
// grid: (L/64, B*H). block: 256 threads (16x16), each owns a 4x4 tile.
__global__ void __launch_bounds__(256)
flash_attn(const float* __restrict__ qkv, float* __restrict__ out) {
    __shared__ float Qs[64][64];   // Q tile, [row][d]
    __shared__ float Ks[64][64];   // K tile transposed [d][key]; reused as P [row][key]
    __shared__ float Vs[64][64];   // V tile [key][d]

    int tid = threadIdx.x;
    int tx = tid & 15;
    int ty = tid >> 4;
    int q0 = blockIdx.x * 64;
    int bh = blockIdx.y;
    int b = bh >> 3;
    int h = bh & 7;
    int qoff = h * 64;
    int koff = 512 + h * 64;
    int voff = 1024 + h * 64;

    // load Q tile (vectorized)
    for (int i = tid; i < 64 * 16; i += 256) {
        int r = i >> 4;
        int c4 = (i & 15) * 4;
        float4 v = *(const float4*)&qkv[((size_t)((q0 + r) * BBATCH + b)) * 1536 + qoff + c4];
        *(float4*)&Qs[r][c4] = v;
    }

    float m_i[4], l_i[4], o[4][4];
#pragma unroll
    for (int i = 0; i < 4; i++) {
        m_i[i] = -1e30f; l_i[i] = 0.0f;
#pragma unroll
        for (int j = 0; j < 4; j++) o[i][j] = 0.0f;
    }
    float* Ps = &Ks[0][0];

    for (int kt = 0; kt < LL / 64; kt++) {
        __syncthreads();  // protect Ks/Vs from previous iteration (and Qs load on iter 0)
        int k0 = kt * 64;
        for (int i = tid; i < 64 * 16; i += 256) {
            int r = i >> 4;
            int c4 = (i & 15) * 4;
            size_t base = ((size_t)((k0 + r) * BBATCH + b)) * 1536;
            float4 kv = *(const float4*)&qkv[base + koff + c4];
            Ks[c4 + 0][r] = kv.x; Ks[c4 + 1][r] = kv.y;
            Ks[c4 + 2][r] = kv.z; Ks[c4 + 3][r] = kv.w;
            float4 vv = *(const float4*)&qkv[base + voff + c4];
            *(float4*)&Vs[r][c4] = vv;
        }
        __syncthreads();

        // S = Q K^T * 1/8
        float s[4][4];
#pragma unroll
        for (int i = 0; i < 4; i++)
#pragma unroll
            for (int j = 0; j < 4; j++) s[i][j] = 0.0f;

        for (int d = 0; d < 64; d++) {
            float4 k4 = *(const float4*)&Ks[d][tx * 4];
            float kv[4] = {k4.x, k4.y, k4.z, k4.w};
#pragma unroll
            for (int i = 0; i < 4; i++) {
                float qv = Qs[ty * 4 + i][d];
#pragma unroll
                for (int j = 0; j < 4; j++)
                    s[i][j] = fmaf(qv, kv[j], s[i][j]);
            }
        }

        // online softmax update (row groups of 16 threads share a row)
#pragma unroll
        for (int i = 0; i < 4; i++) {
#pragma unroll
            for (int j = 0; j < 4; j++) s[i][j] *= 0.125f;
            float mx = fmaxf(fmaxf(s[i][0], s[i][1]), fmaxf(s[i][2], s[i][3]));
#pragma unroll
            for (int off = 1; off < 16; off <<= 1)
                mx = fmaxf(mx, __shfl_xor_sync(0xffffffffu, mx, off));
            float mn = fmaxf(m_i[i], mx);
            float sc = expf(m_i[i] - mn);
            float rs = 0.0f;
#pragma unroll
            for (int j = 0; j < 4; j++) { s[i][j] = expf(s[i][j] - mn); rs += s[i][j]; }
#pragma unroll
            for (int off = 1; off < 16; off <<= 1)
                rs += __shfl_xor_sync(0xffffffffu, rs, off);
            l_i[i] = l_i[i] * sc + rs;
#pragma unroll
            for (int j = 0; j < 4; j++) o[i][j] *= sc;
            m_i[i] = mn;
        }

        __syncthreads();  // all reads of Ks (as K) complete
#pragma unroll
        for (int i = 0; i < 4; i++)
#pragma unroll
            for (int j = 0; j < 4; j++)
                Ps[(ty * 4 + i) * 64 + tx * 4 + j] = s[i][j];
        __syncthreads();

        // O += P V
        for (int m = 0; m < 64; m++) {
            float4 v4 = *(const float4*)&Vs[m][tx * 4];
            float vv[4] = {v4.x, v4.y, v4.z, v4.w};
#pragma unroll
            for (int i = 0; i < 4; i++) {
                float pv = Ps[(ty * 4 + i) * 64 + m];
#pragma unroll
                for (int j = 0; j < 4; j++)
                    o[i][j] = fmaf(pv, vv[j], o[i][j]);
            }
        }
    }

    // write O / l
#pragma unroll
    for (int i = 0; i < 4; i++) {
        float inv = 1.0f / l_i[i];
        float4 o4 = {o[i][0] * inv, o[i][1] * inv, o[i][2] * inv, o[i][3] * inv};
        size_t t = (size_t)((q0 + ty * 4 + i) * BBATCH + b);
        *(float4*)&out[t * EE + h * 64 + tx * 4] = o4;
    }
}

// ---------------- kernel 4: residual add + layernorm ----------------
// one block per token, 256 threads, E=512 (2 elems/thread), two-pass mean/var
__global__ void __launch_bounds__(256)
add_ln_kernel(const float* __restrict__ a, const float* __restrict__ r,
              const float* __restrict__ g, const float* __restrict__ beta,
              float* __restrict__ out) {
    __shared__ float red[8];
    int t = blockIdx.x;
    int tid = threadIdx.x;
    const float* pa = a + (size_t)t * EE;
    const float* pr = r + (size_t)t * EE;
    float v0 = pa[tid] + pr[tid];
    float v1 = pa[tid + 256] + pr[tid + 256];

    float sum = v0 + v1;
#pragma unroll
    for (int off = 16; off > 0; off >>= 1)
        sum += __shfl_xor_sync(0xffffffffu, sum, off);
    if ((tid & 31) == 0) red[tid >> 5] = sum;
    __syncthreads();
    float tot = 0.0f;
#pragma unroll
    for (int w = 0; w < 8; w++) tot += red[w];
    float mu = tot * (1.0f / 512.0f);
    __syncthreads();

    float d0 = v0 - mu, d1 = v1 - mu;
    float sq = d0 * d0 + d1 * d1;
#pragma unroll
    for (int off = 16; off > 0; off >>= 1)
        sq += __shfl_xor_sync(0xffffffffu, sq, off);
    if ((tid & 31) == 0) red[tid >> 5] = sq;
    __syncthreads();
    float vt = 0.0f;
#pragma unroll
    for (int w = 0; w < 8; w++) vt += red[w];
    float var = vt * (1.0f / 512.0f);
    float rstd = rsqrtf(var + 1e-5f);

    out[(size_t)t * EE + tid]       = d0 * rstd * g[tid]       + beta[tid];
    out[(size_t)t * EE + tid + 256] = d1 * rstd * g[tid + 256] + beta[tid + 256];
}

// ---------------- launch ----------------
extern "C" void kernel_launch(void* const* d_in, const int* in_sizes, int n_in,
                              void* d_out, int out_size) {
    const float* x     = (const float*)d_in[0];
    const float* in_w  = (const float*)d_in[1];
    const float* in_b  = (const float*)d_in[2];
    const float* out_w = (const float*)d_in[3];
    const float* out_b = (const float*)d_in[4];
    const float* w1    = (const float*)d_in[5];
    const float* b1    = (const float*)d_in[6];
    const float* w2    = (const float*)d_in[7];
    const float* b2    = (const float*)d_in[8];
    const float* ln_g  = (const float*)d_in[9];
    const float* ln_b  = (const float*)d_in[10];
    float* out = (float*)d_out;

    float *x0, *qkv, *att, *proj, *x1, *hbuf;
    cudaGetSymbolAddress((void**)&x0,   g_x0);
    cudaGetSymbolAddress((void**)&qkv,  g_qkv);
    cudaGetSymbolAddress((void**)&att,  g_att);
    cudaGetSymbolAddress((void**)&proj, g_proj);
    cudaGetSymbolAddress((void**)&x1,   g_x1);
    cudaGetSymbolAddress((void**)&hbuf, g_h);

    // 1. x0 = x + pe
    pe_add_kernel<<<(TT * EE) / 256, 256>>>(x, x0);
    // 2. qkv = x0 @ in_w^T + in_b
    sgemm_nt<0><<<dim3(1536 / 128, TT / 128), 256>>>(x0, in_w, in_b, qkv, TT, 1536, 512);
    // 3. attention
    flash_attn<<<dim3(LL / 64, BBATCH * HH), 256>>>(qkv, att);
    // 4. proj = att @ out_w^T + out_b
    sgemm_nt<0><<<dim3(512 / 128, TT / 128), 256>>>(att, out_w, out_b, proj, TT, 512, 512);
    // 5. x1 = LN(proj + x0)
    add_ln_kernel<<<TT, 256>>>(proj, x0, ln_g, ln_b, x1);
    // 6. h = gelu(x1 @ w1^T + b1)
    sgemm_nt<1><<<dim3(2048 / 128, TT / 128), 256>>>(x1, w1, b1, hbuf, TT, 2048, 512);
    // 7. ff = h @ w2^T + b2   (reuse att buffer)
    sgemm_nt<0><<<dim3(512 / 128, TT / 128), 256>>>(hbuf, w2, b2, att, TT, 512, 2048);
    // 8. out = LN(ff + x1)
    add_ln_kernel<<<TT, 256>>>(att, x1, ln_g, ln_b, out);
}